// round 9
// baseline (speedup 1.0000x reference)
#include <cuda_runtime.h>
#include <cuda_bf16.h>
#include <cuda_fp16.h>
#include <math.h>
#include <stdint.h>

// Problem constants (fixed by the dataset)
#define NN 100000
#define EE 3200000
#define FD 128    // in/hidden feature dim
#define CD 32     // classes
#define NTILES ((NN + 255) / 256)   // 391

// SMEM row stride for bf16 tiles (128 data + 8 pad => conflict-free ldmatrix)
#define KS 136

// ---------------------------------------------------------------------------
// Scratch (static device globals: no allocation allowed in kernel_launch)
// ---------------------------------------------------------------------------
__device__ __half g_H[NN * FD];           // ping buffer (fp16)      25.6 MB
__device__ __half g_H2[NN * FD];          // pong buffer (fp16)      25.6 MB
__device__ __nv_bfloat16 g_Ahi[NN * FD];  // layer-1 input hi (bf16) 25.6 MB
__device__ __nv_bfloat16 g_Alo[NN * FD];  // layer-1 input lo (bf16) 25.6 MB
__device__ float g_dinv[NN];
__device__ int   g_cnt[NN];
__device__ int   g_off[NN + 1];
__device__ int   g_cursor[NN];
__device__ int   g_tileSum[NTILES];
__device__ int   g_tileBase[NTILES];
__device__ int2  g_csr[EE];               // (src, weight bits)      25.6 MB
__device__ int   g_is64;
__device__ __nv_bfloat16 g_Whi[3][FD * FD];   // transposed [N][K] bf16 hi
__device__ __nv_bfloat16 g_Wlo[3][FD * FD];   // transposed [N][K] bf16 lo
__device__ __nv_bfloat16 g_W4hi[CD * FD];
__device__ __nv_bfloat16 g_W4lo[CD * FD];

// ---------------------------------------------------------------------------
// Warp MMA + cp.async helpers (baseline PTX, sm_80+: no 'a'-feature required)
// ---------------------------------------------------------------------------
__device__ __forceinline__ uint32_t smem_to_u32(const void* p) {
    uint32_t a;
    asm("{ .reg .u64 t; cvta.to.shared.u64 t, %1; cvt.u32.u64 %0, t; }"
        : "=r"(a) : "l"(p));
    return a;
}

__device__ __forceinline__ void ldsm_x4(uint32_t& r0, uint32_t& r1,
                                        uint32_t& r2, uint32_t& r3,
                                        uint32_t saddr) {
    asm volatile("ldmatrix.sync.aligned.m8n8.x4.shared.b16 {%0,%1,%2,%3}, [%4];"
                 : "=r"(r0), "=r"(r1), "=r"(r2), "=r"(r3) : "r"(saddr));
}

__device__ __forceinline__ void mma16816(float* c, const uint32_t* a,
                                         const uint32_t* b) {
    asm volatile(
        "mma.sync.aligned.m16n8k16.row.col.f32.bf16.bf16.f32 "
        "{%0,%1,%2,%3}, {%4,%5,%6,%7}, {%8,%9}, {%0,%1,%2,%3};"
        : "+f"(c[0]), "+f"(c[1]), "+f"(c[2]), "+f"(c[3])
        : "r"(a[0]), "r"(a[1]), "r"(a[2]), "r"(a[3]), "r"(b[0]), "r"(b[1]));
}

__device__ __forceinline__ void cp_async16(uint32_t sdst, const void* gsrc, int sz) {
    asm volatile("cp.async.cg.shared.global [%0], [%1], 16, %2;"
                 :: "r"(sdst), "l"(gsrc), "r"(sz) : "memory");
}
#define CP_COMMIT() asm volatile("cp.async.commit_group;" ::: "memory")
#define CP_WAIT(n)  asm volatile("cp.async.wait_group %0;" :: "n"(n) : "memory")

// ---------------------------------------------------------------------------
// Preprocessing (CSR build)
// ---------------------------------------------------------------------------
__global__ void k_detect_dtype(const long long* __restrict__ ei) {
    if (blockIdx.x == 0 && threadIdx.x == 0) {
        int ok = 1;
        for (int i = 0; i < 128; i++) {
            long long v = ei[i];
            if (v < 0 || v >= (long long)NN) { ok = 0; break; }
        }
        g_is64 = ok;
    }
}

__global__ void k_zero_cnt(int* __restrict__ cnt) {
    int i = blockIdx.x * blockDim.x + threadIdx.x;
    if (i < NN) cnt[i] = 0;
}

__global__ void k_hist(const long long* __restrict__ ei, int* __restrict__ cnt) {
    int e = blockIdx.x * blockDim.x + threadIdx.x;
    if (e >= EE) return;
    int d = g_is64 ? (int)ei[EE + e] : ((const int*)ei)[EE + e];
    atomicAdd(&cnt[d], 1);
}

__global__ void k_dinv(const int* __restrict__ cnt, float* __restrict__ dinv) {
    int i = blockIdx.x * blockDim.x + threadIdx.x;
    if (i < NN) dinv[i] = rsqrtf((float)(cnt[i] + 1));  // +1 self-loop
}

__global__ void k_tile_sums(const int* __restrict__ cnt, int* __restrict__ tileSum) {
    __shared__ int sh[256];
    int t = threadIdx.x;
    int i = blockIdx.x * 256 + t;
    sh[t] = (i < NN) ? cnt[i] : 0;
    __syncthreads();
#pragma unroll
    for (int s = 128; s > 0; s >>= 1) {
        if (t < s) sh[t] += sh[t + s];
        __syncthreads();
    }
    if (t == 0) tileSum[blockIdx.x] = sh[0];
}

__global__ void k_scan_tilesums(const int* __restrict__ tileSum,
                                int* __restrict__ tileBase) {
    __shared__ int sh[512];
    int t = threadIdx.x;
    int v = (t < NTILES) ? tileSum[t] : 0;
    sh[t] = v;
    __syncthreads();
#pragma unroll
    for (int o = 1; o < 512; o <<= 1) {
        int a = (t >= o) ? sh[t - o] : 0;
        __syncthreads();
        sh[t] += a;
        __syncthreads();
    }
    if (t < NTILES) tileBase[t] = sh[t] - v;   // exclusive
}

__global__ void k_scan_within(const int* __restrict__ cnt,
                              const int* __restrict__ tileBase,
                              int* __restrict__ off, int* __restrict__ cursor) {
    __shared__ int sh[256];
    int t = threadIdx.x;
    int i = blockIdx.x * 256 + t;
    int v = (i < NN) ? cnt[i] : 0;
    sh[t] = v;
    __syncthreads();
#pragma unroll
    for (int o = 1; o < 256; o <<= 1) {
        int a = (t >= o) ? sh[t - o] : 0;
        __syncthreads();
        sh[t] += a;
        __syncthreads();
    }
    int incl = sh[t];
    if (i < NN) {
        int ex = tileBase[blockIdx.x] + incl - v;
        off[i] = ex;
        cursor[i] = ex;
        if (i == NN - 1) off[NN] = tileBase[blockIdx.x] + incl;
    }
}

__global__ void k_fill(const long long* __restrict__ ei,
                       const float* __restrict__ dinv,
                       int* __restrict__ cursor,
                       int2* __restrict__ csr) {
    int e = blockIdx.x * blockDim.x + threadIdx.x;
    if (e >= EE) return;
    int s, d;
    if (g_is64) {
        s = (int)ei[e];
        d = (int)ei[EE + e];
    } else {
        const int* ei32 = (const int*)ei;
        s = ei32[e];
        d = ei32[EE + e];
    }
    int pos = atomicAdd(&cursor[d], 1);
    csr[pos] = make_int2(s, __float_as_int(dinv[s] * dinv[d]));
}

// ---------------------------------------------------------------------------
// bf16 hi/lo splits
// ---------------------------------------------------------------------------
__device__ __forceinline__ void split2(float a, float b, uint32_t& h, uint32_t& l) {
    __nv_bfloat16 ha = __float2bfloat16(a);
    __nv_bfloat16 hb = __float2bfloat16(b);
    __nv_bfloat16 la = __float2bfloat16(a - __bfloat162float(ha));
    __nv_bfloat16 lb = __float2bfloat16(b - __bfloat162float(hb));
    __nv_bfloat162 hp = __halves2bfloat162(ha, hb);
    __nv_bfloat162 lp = __halves2bfloat162(la, lb);
    h = reinterpret_cast<uint32_t&>(hp);
    l = reinterpret_cast<uint32_t&>(lp);
}

__global__ void k_splitX(const float* __restrict__ x,
                         __nv_bfloat16* __restrict__ hi,
                         __nv_bfloat16* __restrict__ lo) {
    int idx = blockIdx.x * blockDim.x + threadIdx.x;   // per float4
    if (idx >= NN * FD / 4) return;
    float4 v = *(const float4*)(x + (size_t)idx * 4);
    uint2 hh, ll;
    split2(v.x, v.y, hh.x, ll.x);
    split2(v.z, v.w, hh.y, ll.y);
    *(uint2*)(hi + (size_t)idx * 4) = hh;
    *(uint2*)(lo + (size_t)idx * 4) = ll;
}

// Transposed weight split: out[n*128 + k] = split(W[k*Ncols + n])
__global__ void k_splitW(const float* __restrict__ W,
                         __nv_bfloat16* __restrict__ hi,
                         __nv_bfloat16* __restrict__ lo, int Ncols) {
    int idx = blockIdx.x * blockDim.x + threadIdx.x;
    if (idx >= Ncols * FD) return;
    int n = idx / FD, k = idx % FD;
    float v = W[(size_t)k * Ncols + n];
    __nv_bfloat16 h = __float2bfloat16(v);
    hi[idx] = h;
    lo[idx] = __float2bfloat16(v - __bfloat162float(h));
}

// ---------------------------------------------------------------------------
// fp16 gather accumulate helper
// ---------------------------------------------------------------------------
__device__ __forceinline__ void acc_h4(float4& acc, float w, uint2 raw) {
    __half2 p0 = reinterpret_cast<__half2&>(raw.x);
    __half2 p1 = reinterpret_cast<__half2&>(raw.y);
    float2 f0 = __half22float2(p0);
    float2 f1 = __half22float2(p1);
    acc.x = fmaf(f0.x, w, acc.x);
    acc.y = fmaf(f0.y, w, acc.y);
    acc.z = fmaf(f1.x, w, acc.z);
    acc.w = fmaf(f1.y, w, acc.w);
}

// ---------------------------------------------------------------------------
// Layer-1 GEMM (mma.sync bf16, 3-term split, fp32 accum, fp16 output).
// cp.async double-buffered K staging (2 x K=64 stages). A from Ahi/Alo.
// ---------------------------------------------------------------------------
__global__ void __launch_bounds__(256, 1)
k_mma1(const __nv_bfloat16* __restrict__ Ahi, const __nv_bfloat16* __restrict__ Alo,
       const __nv_bfloat16* __restrict__ Bhi, const __nv_bfloat16* __restrict__ Blo,
       __half* __restrict__ H, int M) {
    constexpr int BN = 128, WM = 4, WN = 2, MA = 2, NA = 8;

    extern __shared__ char smem[];
    const uint32_t sb  = smem_to_u32(smem);
    const uint32_t sAH = sb;
    const uint32_t sAL = sAH + 128 * KS * 2;
    const uint32_t sBH = sAL + 128 * KS * 2;
    const uint32_t sBL = sBH + BN * KS * 2;

    const int tid  = threadIdx.x;
    const int wid  = tid >> 5;
    const int lane = tid & 31;
    const int row0 = blockIdx.x * 128;
    const int wm   = wid % WM;
    const int wn   = wid / WM;
    const int rbase = wm * 32;
    const int cbase = wn * 64;

    int rows_valid = M - row0;
    if (rows_valid > 128) rows_valid = 128;
    const __nv_bfloat16* Ah = Ahi + (size_t)row0 * 128;
    const __nv_bfloat16* Al = Alo + (size_t)row0 * 128;

    auto stage = [&](int s) {
        for (int idx = tid; idx < 128 * 8; idx += 256) {
            int row = idx >> 3;
            int c   = s * 8 + (idx & 7);
            uint32_t o = (uint32_t)(row * KS + c * 8) * 2;
            int sz = (row < rows_valid) ? 16 : 0;
            cp_async16(sAH + o, Ah + (size_t)row * 128 + c * 8, sz);
            cp_async16(sAL + o, Al + (size_t)row * 128 + c * 8, sz);
        }
        for (int idx = tid; idx < BN * 8; idx += 256) {
            int row = idx >> 3;
            int c   = s * 8 + (idx & 7);
            uint32_t o = (uint32_t)(row * KS + c * 8) * 2;
            cp_async16(sBH + o, Bhi + (size_t)row * 128 + c * 8, 16);
            cp_async16(sBL + o, Blo + (size_t)row * 128 + c * 8, 16);
        }
    };
    stage(0); CP_COMMIT();
    stage(1); CP_COMMIT();

    float acc[MA][NA][4];
#pragma unroll
    for (int i = 0; i < MA; i++)
#pragma unroll
        for (int j = 0; j < NA; j++)
#pragma unroll
            for (int q = 0; q < 4; q++) acc[i][j][q] = 0.0f;

    const int aq   = lane >> 3;
    const int aw   = lane & 7;
    const int arow = (aq & 1) * 8 + aw;
    const int acol = (aq >> 1) * 8;
    const int brow = (aq >> 1) * 8 + aw;
    const int bcol = (aq & 1) * 8;

    auto compute = [&](int ko) {
        const int k0 = ko * 16;
        uint32_t ah[MA][4], al[MA][4];
#pragma unroll
        for (int ma = 0; ma < MA; ma++) {
            uint32_t off = (uint32_t)((rbase + ma * 16 + arow) * KS + k0 + acol) * 2;
            ldsm_x4(ah[ma][0], ah[ma][1], ah[ma][2], ah[ma][3], sAH + off);
            ldsm_x4(al[ma][0], al[ma][1], al[ma][2], al[ma][3], sAL + off);
        }
        uint32_t bh[NA][2], bl[NA][2];
#pragma unroll
        for (int nbp = 0; nbp < NA / 2; nbp++) {
            uint32_t off = (uint32_t)((cbase + nbp * 16 + brow) * KS + k0 + bcol) * 2;
            ldsm_x4(bh[nbp * 2][0], bh[nbp * 2][1],
                    bh[nbp * 2 + 1][0], bh[nbp * 2 + 1][1], sBH + off);
            ldsm_x4(bl[nbp * 2][0], bl[nbp * 2][1],
                    bl[nbp * 2 + 1][0], bl[nbp * 2 + 1][1], sBL + off);
        }
#pragma unroll
        for (int ma = 0; ma < MA; ma++)
#pragma unroll
            for (int na = 0; na < NA; na++) {
                mma16816(acc[ma][na], ah[ma], bh[na]);
                mma16816(acc[ma][na], ah[ma], bl[na]);
                mma16816(acc[ma][na], al[ma], bh[na]);
            }
    };

    CP_WAIT(1);
    __syncthreads();
#pragma unroll
    for (int ko = 0; ko < 4; ko++) compute(ko);
    CP_WAIT(0);
    __syncthreads();
#pragma unroll
    for (int ko = 4; ko < 8; ko++) compute(ko);

    const int crow = lane >> 2;
    const int ccol = (lane & 3) * 2;
#pragma unroll
    for (int ma = 0; ma < MA; ma++) {
        int r0 = row0 + rbase + ma * 16 + crow;
        int r1 = r0 + 8;
        bool ok0 = r0 < M, ok1 = r1 < M;
#pragma unroll
        for (int na = 0; na < NA; na++) {
            int c = cbase + na * 8 + ccol;
            if (ok0) *(__half2*)&H[(size_t)r0 * BN + c] =
                         __floats2half2_rn(acc[ma][na][0], acc[ma][na][1]);
            if (ok1) *(__half2*)&H[(size_t)r1 * BN + c] =
                         __floats2half2_rn(acc[ma][na][2], acc[ma][na][3]);
        }
    }
}

// ---------------------------------------------------------------------------
// Fused layer: agg(prev layer, bias, ReLU) -> SMEM bf16 split -> GEMM -> Hout.
// One CTA per 128-node tile; 8 warps aggregate 16 nodes each, then MMA.
// Weight B-tiles stream via cp.async during the agg phase.
// ---------------------------------------------------------------------------
template <int BN>
__global__ void __launch_bounds__(256, 1)
k_fused(const __half* __restrict__ Hin, __half* __restrict__ Hout,
        const __nv_bfloat16* __restrict__ Bhi, const __nv_bfloat16* __restrict__ Blo,
        const int2* __restrict__ csr, const int* __restrict__ off,
        const float* __restrict__ dinv, const float* __restrict__ bias, int M) {
    constexpr int WM = (BN == 128) ? 4 : 8;
    constexpr int WN = 8 / WM;
    constexpr int MA = 128 / (WM * 16);
    constexpr int NA = (BN / WN) / 8;

    extern __shared__ char smem[];
    const uint32_t sb  = smem_to_u32(smem);
    const uint32_t sAH = sb;
    const uint32_t sAL = sAH + 128 * KS * 2;
    const uint32_t sBH = sAL + 128 * KS * 2;
    const uint32_t sBL = sBH + BN * KS * 2;

    const int tid  = threadIdx.x;
    const int wid  = tid >> 5;
    const int lane = tid & 31;
    const int row0 = blockIdx.x * 128;

    // --- kick off weight tile loads (overlapped with the agg phase) ---
    for (int idx = tid; idx < BN * 16; idx += 256) {
        int row = idx >> 4, c = idx & 15;
        uint32_t o = (uint32_t)(row * KS + c * 8) * 2;
        cp_async16(sBH + o, Bhi + (size_t)row * 128 + c * 8, 16);
        cp_async16(sBL + o, Blo + (size_t)row * 128 + c * 8, 16);
    }
    CP_COMMIT();

    // --- agg phase: warp w handles local rows [w*16, w*16+16) ---
#pragma unroll 1
    for (int q = 0; q < 16; q++) {
        int iloc = wid * 16 + q;
        int i = row0 + iloc;
        uint32_t oA = (uint32_t)(iloc * KS + lane * 4) * 2;
        if (i < M) {
            float dv = dinv[i];
            float w0 = dv * dv;
            float4 acc = *(const float4*)&bias[lane * 4];
            acc_h4(acc, w0, *(const uint2*)(Hin + (size_t)i * 128 + lane * 4));

            int beg = off[i], end = off[i + 1];
            int j = beg;
            for (; j + 8 <= end; j += 8) {
                int2 e[8];
                uint2 r[8];
#pragma unroll
                for (int u = 0; u < 8; u++) e[u] = csr[j + u];
#pragma unroll
                for (int u = 0; u < 8; u++)
                    r[u] = *(const uint2*)(Hin + (size_t)e[u].x * 128 + lane * 4);
#pragma unroll
                for (int u = 0; u < 8; u++)
                    acc_h4(acc, __int_as_float(e[u].y), r[u]);
            }
            for (; j + 2 <= end; j += 2) {
                int2 e0 = csr[j], e1 = csr[j + 1];
                uint2 r0 = *(const uint2*)(Hin + (size_t)e0.x * 128 + lane * 4);
                uint2 r1 = *(const uint2*)(Hin + (size_t)e1.x * 128 + lane * 4);
                acc_h4(acc, __int_as_float(e0.y), r0);
                acc_h4(acc, __int_as_float(e1.y), r1);
            }
            if (j < end) {
                int2 e = csr[j];
                acc_h4(acc, __int_as_float(e.y),
                       *(const uint2*)(Hin + (size_t)e.x * 128 + lane * 4));
            }

            // ReLU + bf16 hi/lo split straight into SMEM A tiles
            float vx = fmaxf(acc.x, 0.f), vy = fmaxf(acc.y, 0.f);
            float vz = fmaxf(acc.z, 0.f), vw = fmaxf(acc.w, 0.f);
            uint2 hh, ll;
            split2(vx, vy, hh.x, ll.x);
            split2(vz, vw, hh.y, ll.y);
            *(uint2*)(smem + (sAH - sb) + oA) = hh;
            *(uint2*)(smem + (sAL - sb) + oA) = ll;
        } else {
            uint2 z = make_uint2(0, 0);
            *(uint2*)(smem + (sAH - sb) + oA) = z;
            *(uint2*)(smem + (sAL - sb) + oA) = z;
        }
    }

    CP_WAIT(0);
    __syncthreads();

    // --- MMA phase ---
    const int wm   = wid % WM;
    const int wn   = wid / WM;
    const int rbase = wm * (128 / WM);
    const int cbase = wn * (BN / WN);

    float acc[MA][NA][4];
#pragma unroll
    for (int i = 0; i < MA; i++)
#pragma unroll
        for (int j = 0; j < NA; j++)
#pragma unroll
            for (int q = 0; q < 4; q++) acc[i][j][q] = 0.0f;

    const int aq   = lane >> 3;
    const int aw   = lane & 7;
    const int arow = (aq & 1) * 8 + aw;
    const int acol = (aq >> 1) * 8;
    const int brow = (aq >> 1) * 8 + aw;
    const int bcol = (aq & 1) * 8;

#pragma unroll
    for (int ko = 0; ko < 8; ko++) {
        const int k0 = ko * 16;
        uint32_t ah[MA][4], al[MA][4];
#pragma unroll
        for (int ma = 0; ma < MA; ma++) {
            uint32_t offA = (uint32_t)((rbase + ma * 16 + arow) * KS + k0 + acol) * 2;
            ldsm_x4(ah[ma][0], ah[ma][1], ah[ma][2], ah[ma][3], sAH + offA);
            ldsm_x4(al[ma][0], al[ma][1], al[ma][2], al[ma][3], sAL + offA);
        }
        uint32_t bh[NA][2], bl[NA][2];
#pragma unroll
        for (int nbp = 0; nbp < NA / 2; nbp++) {
            uint32_t offB = (uint32_t)((cbase + nbp * 16 + brow) * KS + k0 + bcol) * 2;
            ldsm_x4(bh[nbp * 2][0], bh[nbp * 2][1],
                    bh[nbp * 2 + 1][0], bh[nbp * 2 + 1][1], sBH + offB);
            ldsm_x4(bl[nbp * 2][0], bl[nbp * 2][1],
                    bl[nbp * 2 + 1][0], bl[nbp * 2 + 1][1], sBL + offB);
        }
#pragma unroll
        for (int ma = 0; ma < MA; ma++)
#pragma unroll
            for (int na = 0; na < NA; na++) {
                mma16816(acc[ma][na], ah[ma], bh[na]);
                mma16816(acc[ma][na], ah[ma], bl[na]);
                mma16816(acc[ma][na], al[ma], bh[na]);
            }
    }

    const int crow = lane >> 2;
    const int ccol = (lane & 3) * 2;
#pragma unroll
    for (int ma = 0; ma < MA; ma++) {
        int r0 = row0 + rbase + ma * 16 + crow;
        int r1 = r0 + 8;
        bool ok0 = r0 < M, ok1 = r1 < M;
#pragma unroll
        for (int na = 0; na < NA; na++) {
            int c = cbase + na * 8 + ccol;
            if (ok0) *(__half2*)&Hout[(size_t)r0 * BN + c] =
                         __floats2half2_rn(acc[ma][na][0], acc[ma][na][1]);
            if (ok1) *(__half2*)&Hout[(size_t)r1 * BN + c] =
                         __floats2half2_rn(acc[ma][na][2], acc[ma][na][3]);
        }
    }
}

// ---------------------------------------------------------------------------
// Final CSR aggregation, 32-dim + fused log-softmax: 8 lanes per node.
// ---------------------------------------------------------------------------
__global__ void k_agg32_lsm(const __half* __restrict__ H, float* __restrict__ out,
                            const int2* __restrict__ csr,
                            const int* __restrict__ off,
                            const float* __restrict__ dinv,
                            const float* __restrict__ bias) {
    int t = blockIdx.x * blockDim.x + threadIdx.x;
    int i = t >> 3;
    if (i >= NN) return;
    int sub = t & 7;

    float dv = dinv[i];
    float w0 = dv * dv;
    float4 acc = *(const float4*)&bias[sub * 4];
    acc_h4(acc, w0, *(const uint2*)(H + (size_t)i * 32 + sub * 4));

    int beg = off[i], end = off[i + 1];
    int j = beg;
    for (; j + 4 <= end; j += 4) {
        int2 e0 = csr[j],     e1 = csr[j + 1];
        int2 e2 = csr[j + 2], e3 = csr[j + 3];
        uint2 r0 = *(const uint2*)(H + (size_t)e0.x * 32 + sub * 4);
        uint2 r1 = *(const uint2*)(H + (size_t)e1.x * 32 + sub * 4);
        uint2 r2 = *(const uint2*)(H + (size_t)e2.x * 32 + sub * 4);
        uint2 r3 = *(const uint2*)(H + (size_t)e3.x * 32 + sub * 4);
        acc_h4(acc, __int_as_float(e0.y), r0);
        acc_h4(acc, __int_as_float(e1.y), r1);
        acc_h4(acc, __int_as_float(e2.y), r2);
        acc_h4(acc, __int_as_float(e3.y), r3);
    }
    for (; j < end; j++) {
        int2 e = csr[j];
        acc_h4(acc, __int_as_float(e.y),
               *(const uint2*)(H + (size_t)e.x * 32 + sub * 4));
    }

    unsigned m = __activemask();
    float mx = fmaxf(fmaxf(acc.x, acc.y), fmaxf(acc.z, acc.w));
#pragma unroll
    for (int o = 4; o > 0; o >>= 1)
        mx = fmaxf(mx, __shfl_xor_sync(m, mx, o));
    float ex = expf(acc.x - mx) + expf(acc.y - mx) +
               expf(acc.z - mx) + expf(acc.w - mx);
#pragma unroll
    for (int o = 4; o > 0; o >>= 1)
        ex += __shfl_xor_sync(m, ex, o);
    float ls = mx + logf(ex);

    float4 r;
    r.x = acc.x - ls; r.y = acc.y - ls; r.z = acc.z - ls; r.w = acc.w - ls;
    *(float4*)&out[(size_t)i * 32 + sub * 4] = r;
}

// ---------------------------------------------------------------------------
// Launch: CSR build forked onto a side stream, overlapped with splits + GEMM1.
// ---------------------------------------------------------------------------
extern "C" void kernel_launch(void* const* d_in, const int* in_sizes, int n_in,
                              void* d_out, int out_size) {
    const float*     x  = (const float*)d_in[0];
    const long long* ei = (const long long*)d_in[1];
    const float* W1 = (const float*)d_in[2];
    const float* b1 = (const float*)d_in[3];
    const float* W2 = (const float*)d_in[4];
    const float* b2 = (const float*)d_in[5];
    const float* W3 = (const float*)d_in[6];
    const float* b3 = (const float*)d_in[7];
    const float* W4 = (const float*)d_in[8];
    const float* b4 = (const float*)d_in[9];
    float* out = (float*)d_out;

    __half *H0, *H1;
    float *dinv;
    __nv_bfloat16 *Ahi, *Alo, *Whi, *Wlo, *W4hi, *W4lo;
    int *cnt, *off, *cursor, *tileSum, *tileBase;
    int2* csr;
    cudaGetSymbolAddress((void**)&H0,       g_H);
    cudaGetSymbolAddress((void**)&H1,       g_H2);
    cudaGetSymbolAddress((void**)&Ahi,      g_Ahi);
    cudaGetSymbolAddress((void**)&Alo,      g_Alo);
    cudaGetSymbolAddress((void**)&dinv,     g_dinv);
    cudaGetSymbolAddress((void**)&cnt,      g_cnt);
    cudaGetSymbolAddress((void**)&off,      g_off);
    cudaGetSymbolAddress((void**)&cursor,   g_cursor);
    cudaGetSymbolAddress((void**)&tileSum,  g_tileSum);
    cudaGetSymbolAddress((void**)&tileBase, g_tileBase);
    cudaGetSymbolAddress((void**)&csr,      g_csr);
    cudaGetSymbolAddress((void**)&Whi,      g_Whi);
    cudaGetSymbolAddress((void**)&Wlo,      g_Wlo);
    cudaGetSymbolAddress((void**)&W4hi,     g_W4hi);
    cudaGetSymbolAddress((void**)&W4lo,     g_W4lo);

    const int TB = 256;
    const int nblk = NTILES;
    const int eblk = (EE + TB - 1) / TB;

    // dynamic smem: (128 + 128 + BN + BN) rows * KS bf16
    const int SMEM128 = (128 + 128 + 128 + 128) * KS * 2;   // 139264
    const int SMEM32  = (128 + 128 + 32 + 32) * KS * 2;     // 87040
    cudaFuncSetAttribute((const void*)k_mma1,
                         cudaFuncAttributeMaxDynamicSharedMemorySize, SMEM128);
    cudaFuncSetAttribute((const void*)k_fused<128>,
                         cudaFuncAttributeMaxDynamicSharedMemorySize, SMEM128);
    cudaFuncSetAttribute((const void*)k_fused<32>,
                         cudaFuncAttributeMaxDynamicSharedMemorySize, SMEM32);

    // Side stream + fork/join events (created per call; few calls total, and
    // they must outlive graph capture, so they are intentionally not destroyed).
    cudaStream_t s2;
    cudaStreamCreateWithFlags(&s2, cudaStreamNonBlocking);
    cudaEvent_t evFork, evJoin;
    cudaEventCreateWithFlags(&evFork, cudaEventDisableTiming);
    cudaEventCreateWithFlags(&evJoin, cudaEventDisableTiming);

    // --- fork: CSR build on s2 ---
    cudaEventRecord(evFork, 0);
    cudaStreamWaitEvent(s2, evFork, 0);
    k_detect_dtype<<<1, 32, 0, s2>>>(ei);
    k_zero_cnt<<<nblk, TB, 0, s2>>>(cnt);
    k_hist<<<eblk, TB, 0, s2>>>(ei, cnt);
    k_dinv<<<nblk, TB, 0, s2>>>(cnt, dinv);
    k_tile_sums<<<nblk, TB, 0, s2>>>(cnt, tileSum);
    k_scan_tilesums<<<1, 512, 0, s2>>>(tileSum, tileBase);
    k_scan_within<<<nblk, TB, 0, s2>>>(cnt, tileBase, off, cursor);
    k_fill<<<eblk, TB, 0, s2>>>(ei, dinv, cursor, csr);
    cudaEventRecord(evJoin, s2);

    // --- main stream: splits + layer-1 GEMM (independent of CSR) ---
    k_splitX<<<(NN * FD / 4 + TB - 1) / TB, TB>>>(x, Ahi, Alo);
    k_splitW<<<(FD * FD + TB - 1) / TB, TB>>>(W1, Whi + 0 * FD * FD, Wlo + 0 * FD * FD, FD);
    k_splitW<<<(FD * FD + TB - 1) / TB, TB>>>(W2, Whi + 1 * FD * FD, Wlo + 1 * FD * FD, FD);
    k_splitW<<<(FD * FD + TB - 1) / TB, TB>>>(W3, Whi + 2 * FD * FD, Wlo + 2 * FD * FD, FD);
    k_splitW<<<(CD * FD + TB - 1) / TB, TB>>>(W4, W4hi, W4lo, CD);

    const int mma_grid = (NN + 127) / 128;   // 782
    const int agg32_blocks = (NN * 8 + TB - 1) / TB;

    // --- layer 1: H0 = X @ W1 ---
    k_mma1<<<mma_grid, 256, SMEM128>>>(Ahi, Alo, Whi + 0 * FD * FD, Wlo + 0 * FD * FD, H0, NN);
    cudaStreamWaitEvent(0, evJoin, 0);       // join: fused needs csr/off/dinv

    // --- layer 2: H1 = agg(H0, b1, relu) @ W2 ---
    k_fused<128><<<mma_grid, 256, SMEM128>>>(H0, H1,
        Whi + 1 * FD * FD, Wlo + 1 * FD * FD, csr, off, dinv, b1, NN);

    // --- layer 3: H0 = agg(H1, b2, relu) @ W3 ---
    k_fused<128><<<mma_grid, 256, SMEM128>>>(H1, H0,
        Whi + 2 * FD * FD, Wlo + 2 * FD * FD, csr, off, dinv, b2, NN);

    // --- layer 4: H1 = agg(H0, b3, relu) @ W4  (32-dim) ---
    k_fused<32><<<mma_grid, 256, SMEM32>>>(H0, H1,
        W4hi, W4lo, csr, off, dinv, b3, NN);

    // --- final aggregation + log-softmax ---
    k_agg32_lsm<<<agg32_blocks, TB>>>(H1, out, csr, off, dinv, b4);
}

// round 16
// speedup vs baseline: 1.8512x; 1.8512x over previous
#include <cuda_runtime.h>
#include <cuda_bf16.h>
#include <cuda_fp16.h>
#include <math.h>
#include <stdint.h>

// Problem constants (fixed by the dataset)
#define NN 100000
#define EE 3200000
#define FD 128    // in/hidden feature dim
#define CD 32     // classes
#define NTILES ((NN + 255) / 256)   // 391
#define MTILES ((NN + 127) / 128)   // 782

// SMEM row stride for bf16 tiles (128 data + 8 pad => conflict-free ldmatrix)
#define KS 136

// ---------------------------------------------------------------------------
// Scratch (static device globals: no allocation allowed in kernel_launch)
// ---------------------------------------------------------------------------
__device__ __half g_H[NN * FD];           // ping buffer (fp16)      25.6 MB
__device__ __half g_H2[NN * FD];          // pong buffer (fp16)      25.6 MB
__device__ __nv_bfloat16 g_Ghi[NN * FD];  // activation hi (bf16)    25.6 MB
__device__ __nv_bfloat16 g_Glo[NN * FD];  // activation lo (bf16)    25.6 MB
__device__ float g_dinv[NN];
__device__ int   g_cnt[NN];
__device__ int   g_off[NN + 1];
__device__ int   g_cursor[NN];
__device__ int   g_tileSum[NTILES];
__device__ int   g_tileBase[NTILES];
__device__ int2  g_csr[EE];               // (src, weight bits)      25.6 MB
__device__ int   g_is64;
__device__ __nv_bfloat16 g_Whi[3][FD * FD];   // transposed [N][K] bf16 hi
__device__ __nv_bfloat16 g_Wlo[3][FD * FD];   // transposed [N][K] bf16 lo
__device__ __nv_bfloat16 g_W4hi[CD * FD];
__device__ __nv_bfloat16 g_W4lo[CD * FD];

// ---------------------------------------------------------------------------
// Warp MMA + cp.async helpers (baseline PTX, sm_80+: no 'a'-feature required)
// ---------------------------------------------------------------------------
__device__ __forceinline__ uint32_t smem_to_u32(const void* p) {
    uint32_t a;
    asm("{ .reg .u64 t; cvta.to.shared.u64 t, %1; cvt.u32.u64 %0, t; }"
        : "=r"(a) : "l"(p));
    return a;
}

__device__ __forceinline__ void ldsm_x4(uint32_t& r0, uint32_t& r1,
                                        uint32_t& r2, uint32_t& r3,
                                        uint32_t saddr) {
    asm volatile("ldmatrix.sync.aligned.m8n8.x4.shared.b16 {%0,%1,%2,%3}, [%4];"
                 : "=r"(r0), "=r"(r1), "=r"(r2), "=r"(r3) : "r"(saddr));
}

__device__ __forceinline__ void mma16816(float* c, const uint32_t* a,
                                         const uint32_t* b) {
    asm volatile(
        "mma.sync.aligned.m16n8k16.row.col.f32.bf16.bf16.f32 "
        "{%0,%1,%2,%3}, {%4,%5,%6,%7}, {%8,%9}, {%0,%1,%2,%3};"
        : "+f"(c[0]), "+f"(c[1]), "+f"(c[2]), "+f"(c[3])
        : "r"(a[0]), "r"(a[1]), "r"(a[2]), "r"(a[3]), "r"(b[0]), "r"(b[1]));
}

__device__ __forceinline__ void cp_async16(uint32_t sdst, const void* gsrc, int sz) {
    asm volatile("cp.async.cg.shared.global [%0], [%1], 16, %2;"
                 :: "r"(sdst), "l"(gsrc), "r"(sz) : "memory");
}
#define CP_COMMIT() asm volatile("cp.async.commit_group;" ::: "memory")
#define CP_WAIT(n)  asm volatile("cp.async.wait_group %0;" :: "n"(n) : "memory")

// ---------------------------------------------------------------------------
// Preprocessing (CSR build)
// ---------------------------------------------------------------------------
__global__ void k_detect_dtype(const long long* __restrict__ ei) {
    if (blockIdx.x == 0 && threadIdx.x == 0) {
        int ok = 1;
        for (int i = 0; i < 128; i++) {
            long long v = ei[i];
            if (v < 0 || v >= (long long)NN) { ok = 0; break; }
        }
        g_is64 = ok;
    }
}

__global__ void k_zero_cnt(int* __restrict__ cnt) {
    int i = blockIdx.x * blockDim.x + threadIdx.x;
    if (i < NN) cnt[i] = 0;
}

__global__ void k_hist(const long long* __restrict__ ei, int* __restrict__ cnt) {
    int e = blockIdx.x * blockDim.x + threadIdx.x;
    if (e >= EE) return;
    int d = g_is64 ? (int)ei[EE + e] : ((const int*)ei)[EE + e];
    atomicAdd(&cnt[d], 1);
}

__global__ void k_dinv(const int* __restrict__ cnt, float* __restrict__ dinv) {
    int i = blockIdx.x * blockDim.x + threadIdx.x;
    if (i < NN) dinv[i] = rsqrtf((float)(cnt[i] + 1));  // +1 self-loop
}

__global__ void k_tile_sums(const int* __restrict__ cnt, int* __restrict__ tileSum) {
    __shared__ int sh[256];
    int t = threadIdx.x;
    int i = blockIdx.x * 256 + t;
    sh[t] = (i < NN) ? cnt[i] : 0;
    __syncthreads();
#pragma unroll
    for (int s = 128; s > 0; s >>= 1) {
        if (t < s) sh[t] += sh[t + s];
        __syncthreads();
    }
    if (t == 0) tileSum[blockIdx.x] = sh[0];
}

__global__ void k_scan_tilesums(const int* __restrict__ tileSum,
                                int* __restrict__ tileBase) {
    __shared__ int sh[512];
    int t = threadIdx.x;
    int v = (t < NTILES) ? tileSum[t] : 0;
    sh[t] = v;
    __syncthreads();
#pragma unroll
    for (int o = 1; o < 512; o <<= 1) {
        int a = (t >= o) ? sh[t - o] : 0;
        __syncthreads();
        sh[t] += a;
        __syncthreads();
    }
    if (t < NTILES) tileBase[t] = sh[t] - v;   // exclusive
}

__global__ void k_scan_within(const int* __restrict__ cnt,
                              const int* __restrict__ tileBase,
                              int* __restrict__ off, int* __restrict__ cursor) {
    __shared__ int sh[256];
    int t = threadIdx.x;
    int i = blockIdx.x * 256 + t;
    int v = (i < NN) ? cnt[i] : 0;
    sh[t] = v;
    __syncthreads();
#pragma unroll
    for (int o = 1; o < 256; o <<= 1) {
        int a = (t >= o) ? sh[t - o] : 0;
        __syncthreads();
        sh[t] += a;
        __syncthreads();
    }
    int incl = sh[t];
    if (i < NN) {
        int ex = tileBase[blockIdx.x] + incl - v;
        off[i] = ex;
        cursor[i] = ex;
        if (i == NN - 1) off[NN] = tileBase[blockIdx.x] + incl;
    }
}

__global__ void k_fill(const long long* __restrict__ ei,
                       const float* __restrict__ dinv,
                       int* __restrict__ cursor,
                       int2* __restrict__ csr) {
    int e = blockIdx.x * blockDim.x + threadIdx.x;
    if (e >= EE) return;
    int s, d;
    if (g_is64) {
        s = (int)ei[e];
        d = (int)ei[EE + e];
    } else {
        const int* ei32 = (const int*)ei;
        s = ei32[e];
        d = ei32[EE + e];
    }
    int pos = atomicAdd(&cursor[d], 1);
    csr[pos] = make_int2(s, __float_as_int(dinv[s] * dinv[d]));
}

// ---------------------------------------------------------------------------
// bf16 hi/lo splits
// ---------------------------------------------------------------------------
__device__ __forceinline__ void split2(float a, float b, uint32_t& h, uint32_t& l) {
    __nv_bfloat16 ha = __float2bfloat16(a);
    __nv_bfloat16 hb = __float2bfloat16(b);
    __nv_bfloat16 la = __float2bfloat16(a - __bfloat162float(ha));
    __nv_bfloat16 lb = __float2bfloat16(b - __bfloat162float(hb));
    __nv_bfloat162 hp = __halves2bfloat162(ha, hb);
    __nv_bfloat162 lp = __halves2bfloat162(la, lb);
    h = reinterpret_cast<uint32_t&>(hp);
    l = reinterpret_cast<uint32_t&>(lp);
}

// Transposed weight split: out[n*128 + k] = split(W[k*Ncols + n])
__global__ void k_splitW(const float* __restrict__ W,
                         __nv_bfloat16* __restrict__ hi,
                         __nv_bfloat16* __restrict__ lo, int Ncols) {
    int idx = blockIdx.x * blockDim.x + threadIdx.x;
    if (idx >= Ncols * FD) return;
    int n = idx / FD, k = idx % FD;
    float v = W[(size_t)k * Ncols + n];
    __nv_bfloat16 h = __float2bfloat16(v);
    hi[idx] = h;
    lo[idx] = __float2bfloat16(v - __bfloat162float(h));
}

// ---------------------------------------------------------------------------
// fp16 gather accumulate helper
// ---------------------------------------------------------------------------
__device__ __forceinline__ void acc_h4(float4& acc, float w, uint2 raw) {
    __half2 p0 = reinterpret_cast<__half2&>(raw.x);
    __half2 p1 = reinterpret_cast<__half2&>(raw.y);
    float2 f0 = __half22float2(p0);
    float2 f1 = __half22float2(p1);
    acc.x = fmaf(f0.x, w, acc.x);
    acc.y = fmaf(f0.y, w, acc.y);
    acc.z = fmaf(f1.x, w, acc.z);
    acc.w = fmaf(f1.y, w, acc.w);
}

// ---------------------------------------------------------------------------
// Shared MMA compute core (A/B tiles resident in SMEM, 3-term bf16 split)
// ---------------------------------------------------------------------------
template <int BN>
__device__ __forceinline__ void mma_core_store(
    uint32_t sAH, uint32_t sAL, uint32_t sBH, uint32_t sBL,
    __half* __restrict__ H, int row0, int M, int wid, int lane) {
    constexpr int WM = (BN == 128) ? 4 : 8;
    constexpr int WN = 8 / WM;
    constexpr int MA = 128 / (WM * 16);
    constexpr int NA = (BN / WN) / 8;

    const int wm = wid % WM;
    const int wn = wid / WM;
    const int rbase = wm * (128 / WM);
    const int cbase = wn * (BN / WN);

    float acc[MA][NA][4];
#pragma unroll
    for (int i = 0; i < MA; i++)
#pragma unroll
        for (int j = 0; j < NA; j++)
#pragma unroll
            for (int q = 0; q < 4; q++) acc[i][j][q] = 0.0f;

    const int aq   = lane >> 3;
    const int aw   = lane & 7;
    const int arow = (aq & 1) * 8 + aw;
    const int acol = (aq >> 1) * 8;
    const int brow = (aq >> 1) * 8 + aw;
    const int bcol = (aq & 1) * 8;

#pragma unroll
    for (int ko = 0; ko < 8; ko++) {
        const int k0 = ko * 16;
        uint32_t ah[MA][4], al[MA][4];
#pragma unroll
        for (int ma = 0; ma < MA; ma++) {
            uint32_t off = (uint32_t)((rbase + ma * 16 + arow) * KS + k0 + acol) * 2;
            ldsm_x4(ah[ma][0], ah[ma][1], ah[ma][2], ah[ma][3], sAH + off);
            ldsm_x4(al[ma][0], al[ma][1], al[ma][2], al[ma][3], sAL + off);
        }
        uint32_t bh[NA][2], bl[NA][2];
#pragma unroll
        for (int nbp = 0; nbp < NA / 2; nbp++) {
            uint32_t off = (uint32_t)((cbase + nbp * 16 + brow) * KS + k0 + bcol) * 2;
            ldsm_x4(bh[nbp * 2][0], bh[nbp * 2][1],
                    bh[nbp * 2 + 1][0], bh[nbp * 2 + 1][1], sBH + off);
            ldsm_x4(bl[nbp * 2][0], bl[nbp * 2][1],
                    bl[nbp * 2 + 1][0], bl[nbp * 2 + 1][1], sBL + off);
        }
#pragma unroll
        for (int ma = 0; ma < MA; ma++)
#pragma unroll
            for (int na = 0; na < NA; na++) {
                mma16816(acc[ma][na], ah[ma], bh[na]);
                mma16816(acc[ma][na], ah[ma], bl[na]);
                mma16816(acc[ma][na], al[ma], bh[na]);
            }
    }

    const int crow = lane >> 2;
    const int ccol = (lane & 3) * 2;
#pragma unroll
    for (int ma = 0; ma < MA; ma++) {
        int r0 = row0 + rbase + ma * 16 + crow;
        int r1 = r0 + 8;
        bool ok0 = r0 < M, ok1 = r1 < M;
#pragma unroll
        for (int na = 0; na < NA; na++) {
            int c = cbase + na * 8 + ccol;
            if (ok0) *(__half2*)&H[(size_t)r0 * BN + c] =
                         __floats2half2_rn(acc[ma][na][0], acc[ma][na][1]);
            if (ok1) *(__half2*)&H[(size_t)r1 * BN + c] =
                         __floats2half2_rn(acc[ma][na][2], acc[ma][na][3]);
        }
    }
}

// ---------------------------------------------------------------------------
// Layer-1 GEMM with fused X split: loads x fp32, splits to bf16 hi/lo in regs.
// ---------------------------------------------------------------------------
__global__ void __launch_bounds__(256, 1)
k_mma1x(const float* __restrict__ x,
        const __nv_bfloat16* __restrict__ Bhi, const __nv_bfloat16* __restrict__ Blo,
        __half* __restrict__ H, int M) {
    constexpr int BN = 128;
    extern __shared__ char smem[];
    const uint32_t sb  = smem_to_u32(smem);
    const uint32_t sAH = sb;
    const uint32_t sAL = sAH + 128 * KS * 2;
    const uint32_t sBH = sAL + 128 * KS * 2;
    const uint32_t sBL = sBH + BN * KS * 2;

    const int tid  = threadIdx.x;
    const int wid  = tid >> 5;
    const int lane = tid & 31;
    const int row0 = blockIdx.x * 128;

    // B tiles async (overlapped with the fp32 load + register split of A)
    for (int idx = tid; idx < BN * 16; idx += 256) {
        int row = idx >> 4, c = idx & 15;
        uint32_t o = (uint32_t)(row * KS + c * 8) * 2;
        cp_async16(sBH + o, Bhi + (size_t)row * 128 + c * 8, 16);
        cp_async16(sBL + o, Blo + (size_t)row * 128 + c * 8, 16);
    }
    CP_COMMIT();

    // A: load x fp32, split to hi/lo in registers, store to SMEM
    int rows_valid = M - row0;
    if (rows_valid > 128) rows_valid = 128;
    for (int idx = tid; idx < 128 * 32; idx += 256) {   // per float4
        int row = idx >> 5, c4 = idx & 31;
        uint2 hh = make_uint2(0, 0), ll = hh;
        if (row < rows_valid) {
            float4 v = *(const float4*)(x + (size_t)(row0 + row) * 128 + c4 * 4);
            split2(v.x, v.y, hh.x, ll.x);
            split2(v.z, v.w, hh.y, ll.y);
        }
        uint32_t o = (uint32_t)(row * KS + c4 * 4) * 2;
        *(uint2*)(smem + (sAH - sb) + o) = hh;
        *(uint2*)(smem + (sAL - sb) + o) = ll;
    }
    CP_WAIT(0);
    __syncthreads();

    mma_core_store<BN>(sAH, sAL, sBH, sBL, H, row0, M, wid, lane);
}

// ---------------------------------------------------------------------------
// Generic GEMM: A from global Ghi/Glo (bf16 hi/lo), cp.async staging.
// ---------------------------------------------------------------------------
template <int BN>
__global__ void __launch_bounds__(256, 1)
k_mma(const __nv_bfloat16* __restrict__ Ahi, const __nv_bfloat16* __restrict__ Alo,
      const __nv_bfloat16* __restrict__ Bhi, const __nv_bfloat16* __restrict__ Blo,
      __half* __restrict__ H, int M) {
    extern __shared__ char smem[];
    const uint32_t sb  = smem_to_u32(smem);
    const uint32_t sAH = sb;
    const uint32_t sAL = sAH + 128 * KS * 2;
    const uint32_t sBH = sAL + 128 * KS * 2;
    const uint32_t sBL = sBH + BN * KS * 2;

    const int tid  = threadIdx.x;
    const int wid  = tid >> 5;
    const int lane = tid & 31;
    const int row0 = blockIdx.x * 128;

    int rows_valid = M - row0;
    if (rows_valid > 128) rows_valid = 128;
    const __nv_bfloat16* Ah = Ahi + (size_t)row0 * 128;
    const __nv_bfloat16* Al = Alo + (size_t)row0 * 128;

    for (int idx = tid; idx < 128 * 16; idx += 256) {
        int row = idx >> 4, c = idx & 15;
        uint32_t o = (uint32_t)(row * KS + c * 8) * 2;
        int sz = (row < rows_valid) ? 16 : 0;
        cp_async16(sAH + o, Ah + (size_t)row * 128 + c * 8, sz);
        cp_async16(sAL + o, Al + (size_t)row * 128 + c * 8, sz);
    }
    for (int idx = tid; idx < BN * 16; idx += 256) {
        int row = idx >> 4, c = idx & 15;
        uint32_t o = (uint32_t)(row * KS + c * 8) * 2;
        cp_async16(sBH + o, Bhi + (size_t)row * 128 + c * 8, 16);
        cp_async16(sBL + o, Blo + (size_t)row * 128 + c * 8, 16);
    }
    CP_COMMIT();
    CP_WAIT(0);
    __syncthreads();

    mma_core_store<BN>(sAH, sAL, sBH, sBL, H, row0, M, wid, lane);
}

// ---------------------------------------------------------------------------
// CSR aggregation, 128-dim: one warp per dst node, fp16 gather, fp32 accum.
// Writes ReLU'd bf16 hi/lo activation for the next GEMM.
// ---------------------------------------------------------------------------
__global__ void k_agg128(const __half* __restrict__ H,
                         __nv_bfloat16* __restrict__ Ghi,
                         __nv_bfloat16* __restrict__ Glo,
                         const int2* __restrict__ csr,
                         const int* __restrict__ off,
                         const float* __restrict__ dinv,
                         const float* __restrict__ bias) {
    int t = blockIdx.x * blockDim.x + threadIdx.x;
    int i = t >> 5;
    if (i >= NN) return;
    int lane = t & 31;

    float dv = dinv[i];
    float w0 = dv * dv;
    float4 acc = *(const float4*)&bias[lane * 4];
    acc_h4(acc, w0, *(const uint2*)(H + (size_t)i * 128 + lane * 4));

    int beg = off[i], end = off[i + 1];
    int j = beg;
    for (; j + 8 <= end; j += 8) {
        int2 e[8];
        uint2 r[8];
#pragma unroll
        for (int u = 0; u < 8; u++) e[u] = csr[j + u];
#pragma unroll
        for (int u = 0; u < 8; u++)
            r[u] = *(const uint2*)(H + (size_t)e[u].x * 128 + lane * 4);
#pragma unroll
        for (int u = 0; u < 8; u++)
            acc_h4(acc, __int_as_float(e[u].y), r[u]);
    }
    for (; j + 2 <= end; j += 2) {
        int2 e0 = csr[j], e1 = csr[j + 1];
        uint2 r0 = *(const uint2*)(H + (size_t)e0.x * 128 + lane * 4);
        uint2 r1 = *(const uint2*)(H + (size_t)e1.x * 128 + lane * 4);
        acc_h4(acc, __int_as_float(e0.y), r0);
        acc_h4(acc, __int_as_float(e1.y), r1);
    }
    if (j < end) {
        int2 e = csr[j];
        acc_h4(acc, __int_as_float(e.y),
               *(const uint2*)(H + (size_t)e.x * 128 + lane * 4));
    }

    float vx = fmaxf(acc.x, 0.f), vy = fmaxf(acc.y, 0.f);
    float vz = fmaxf(acc.z, 0.f), vw = fmaxf(acc.w, 0.f);
    uint2 hh, ll;
    split2(vx, vy, hh.x, ll.x);
    split2(vz, vw, hh.y, ll.y);
    *(uint2*)(Ghi + (size_t)i * 128 + lane * 4) = hh;
    *(uint2*)(Glo + (size_t)i * 128 + lane * 4) = ll;
}

// ---------------------------------------------------------------------------
// Final CSR aggregation, 32-dim + fused log-softmax: 8 lanes per node.
// ---------------------------------------------------------------------------
__global__ void k_agg32_lsm(const __half* __restrict__ H, float* __restrict__ out,
                            const int2* __restrict__ csr,
                            const int* __restrict__ off,
                            const float* __restrict__ dinv,
                            const float* __restrict__ bias) {
    int t = blockIdx.x * blockDim.x + threadIdx.x;
    int i = t >> 3;
    if (i >= NN) return;
    int sub = t & 7;

    float dv = dinv[i];
    float w0 = dv * dv;
    float4 acc = *(const float4*)&bias[sub * 4];
    acc_h4(acc, w0, *(const uint2*)(H + (size_t)i * 32 + sub * 4));

    int beg = off[i], end = off[i + 1];
    int j = beg;
    for (; j + 4 <= end; j += 4) {
        int2 e0 = csr[j],     e1 = csr[j + 1];
        int2 e2 = csr[j + 2], e3 = csr[j + 3];
        uint2 r0 = *(const uint2*)(H + (size_t)e0.x * 32 + sub * 4);
        uint2 r1 = *(const uint2*)(H + (size_t)e1.x * 32 + sub * 4);
        uint2 r2 = *(const uint2*)(H + (size_t)e2.x * 32 + sub * 4);
        uint2 r3 = *(const uint2*)(H + (size_t)e3.x * 32 + sub * 4);
        acc_h4(acc, __int_as_float(e0.y), r0);
        acc_h4(acc, __int_as_float(e1.y), r1);
        acc_h4(acc, __int_as_float(e2.y), r2);
        acc_h4(acc, __int_as_float(e3.y), r3);
    }
    for (; j < end; j++) {
        int2 e = csr[j];
        acc_h4(acc, __int_as_float(e.y),
               *(const uint2*)(H + (size_t)e.x * 32 + sub * 4));
    }

    unsigned m = __activemask();
    float mx = fmaxf(fmaxf(acc.x, acc.y), fmaxf(acc.z, acc.w));
#pragma unroll
    for (int o = 4; o > 0; o >>= 1)
        mx = fmaxf(mx, __shfl_xor_sync(m, mx, o));
    float ex = expf(acc.x - mx) + expf(acc.y - mx) +
               expf(acc.z - mx) + expf(acc.w - mx);
#pragma unroll
    for (int o = 4; o > 0; o >>= 1)
        ex += __shfl_xor_sync(m, ex, o);
    float ls = mx + logf(ex);

    float4 r;
    r.x = acc.x - ls; r.y = acc.y - ls; r.z = acc.z - ls; r.w = acc.w - ls;
    *(float4*)&out[(size_t)i * 32 + sub * 4] = r;
}

// ---------------------------------------------------------------------------
// Launch: R8-proven topology — ONE side stream (CSR build), TWO events.
// ---------------------------------------------------------------------------
extern "C" void kernel_launch(void* const* d_in, const int* in_sizes, int n_in,
                              void* d_out, int out_size) {
    const float*     x  = (const float*)d_in[0];
    const long long* ei = (const long long*)d_in[1];
    const float* W1 = (const float*)d_in[2];
    const float* b1 = (const float*)d_in[3];
    const float* W2 = (const float*)d_in[4];
    const float* b2 = (const float*)d_in[5];
    const float* W3 = (const float*)d_in[6];
    const float* b3 = (const float*)d_in[7];
    const float* W4 = (const float*)d_in[8];
    const float* b4 = (const float*)d_in[9];
    float* out = (float*)d_out;

    __half *H0, *H1;
    float *dinv;
    __nv_bfloat16 *Ghi, *Glo, *Whi, *Wlo, *W4hi, *W4lo;
    int *cnt, *off, *cursor, *tileSum, *tileBase;
    int2* csr;
    cudaGetSymbolAddress((void**)&H0,       g_H);
    cudaGetSymbolAddress((void**)&H1,       g_H2);
    cudaGetSymbolAddress((void**)&Ghi,      g_Ghi);
    cudaGetSymbolAddress((void**)&Glo,      g_Glo);
    cudaGetSymbolAddress((void**)&dinv,     g_dinv);
    cudaGetSymbolAddress((void**)&cnt,      g_cnt);
    cudaGetSymbolAddress((void**)&off,      g_off);
    cudaGetSymbolAddress((void**)&cursor,   g_cursor);
    cudaGetSymbolAddress((void**)&tileSum,  g_tileSum);
    cudaGetSymbolAddress((void**)&tileBase, g_tileBase);
    cudaGetSymbolAddress((void**)&csr,      g_csr);
    cudaGetSymbolAddress((void**)&Whi,      g_Whi);
    cudaGetSymbolAddress((void**)&Wlo,      g_Wlo);
    cudaGetSymbolAddress((void**)&W4hi,     g_W4hi);
    cudaGetSymbolAddress((void**)&W4lo,     g_W4lo);

    const int TB = 256;
    const int nblk = NTILES;
    const int eblk = (EE + TB - 1) / TB;

    const int SMEM128 = (128 + 128 + 128 + 128) * KS * 2;   // 139264
    const int SMEM32  = (128 + 128 + 32 + 32) * KS * 2;     // 87040
    cudaFuncSetAttribute((const void*)k_mma1x,
                         cudaFuncAttributeMaxDynamicSharedMemorySize, SMEM128);
    cudaFuncSetAttribute((const void*)k_mma<128>,
                         cudaFuncAttributeMaxDynamicSharedMemorySize, SMEM128);
    cudaFuncSetAttribute((const void*)k_mma<32>,
                         cudaFuncAttributeMaxDynamicSharedMemorySize, SMEM32);

    // R8-proven: exactly one side stream + two events (passed the teardown
    // allocation check across three rounds; NOT destroyed — must outlive
    // graph capture, and kernel_launch is invoked only a couple of times).
    cudaStream_t s2;
    cudaStreamCreateWithFlags(&s2, cudaStreamNonBlocking);
    cudaEvent_t evFork, evJoin;
    cudaEventCreateWithFlags(&evFork, cudaEventDisableTiming);
    cudaEventCreateWithFlags(&evJoin, cudaEventDisableTiming);

    // --- fork: CSR build on s2 ---
    cudaEventRecord(evFork, 0);
    cudaStreamWaitEvent(s2, evFork, 0);
    k_detect_dtype<<<1, 32, 0, s2>>>(ei);

    // Main-stream launches 1-4: weight splits -> launch #6 overall = k_mma1x
    k_splitW<<<(FD * FD + TB - 1) / TB, TB>>>(W1, Whi + 0 * FD * FD, Wlo + 0 * FD * FD, FD);
    k_splitW<<<(FD * FD + TB - 1) / TB, TB>>>(W2, Whi + 1 * FD * FD, Wlo + 1 * FD * FD, FD);
    k_splitW<<<(FD * FD + TB - 1) / TB, TB>>>(W3, Whi + 2 * FD * FD, Wlo + 2 * FD * FD, FD);
    k_splitW<<<(CD * FD + TB - 1) / TB, TB>>>(W4, W4hi, W4lo, CD);

    // --- layer 1: H0 = split(x) @ W1 (fused X split) ---
    k_mma1x<<<MTILES, 256, SMEM128>>>(x, Whi + 0 * FD * FD, Wlo + 0 * FD * FD, H0, NN);

    // --- rest of CSR build on s2 (concurrent with splits + GEMM1) ---
    k_zero_cnt<<<nblk, TB, 0, s2>>>(cnt);
    k_hist<<<eblk, TB, 0, s2>>>(ei, cnt);
    k_dinv<<<nblk, TB, 0, s2>>>(cnt, dinv);
    k_tile_sums<<<nblk, TB, 0, s2>>>(cnt, tileSum);
    k_scan_tilesums<<<1, 512, 0, s2>>>(tileSum, tileBase);
    k_scan_within<<<nblk, TB, 0, s2>>>(cnt, tileBase, off, cursor);
    k_fill<<<eblk, TB, 0, s2>>>(ei, dinv, cursor, csr);
    cudaEventRecord(evJoin, s2);
    cudaStreamWaitEvent(0, evJoin, 0);       // join: agg needs csr/off/dinv

    const int agg128_blocks = (NN * 32 + TB - 1) / TB;
    const int agg32_blocks  = (NN * 8 + TB - 1) / TB;

    // --- layer 2 ---
    k_agg128<<<agg128_blocks, TB>>>(H0, Ghi, Glo, csr, off, dinv, b1);
    k_mma<128><<<MTILES, 256, SMEM128>>>(Ghi, Glo, Whi + 1 * FD * FD, Wlo + 1 * FD * FD, H1, NN);

    // --- layer 3 ---
    k_agg128<<<agg128_blocks, TB>>>(H1, Ghi, Glo, csr, off, dinv, b2);
    k_mma<128><<<MTILES, 256, SMEM128>>>(Ghi, Glo, Whi + 2 * FD * FD, Wlo + 2 * FD * FD, H0, NN);

    // --- layer 4 (32 classes) ---
    k_agg128<<<agg128_blocks, TB>>>(H0, Ghi, Glo, csr, off, dinv, b3);
    k_mma<32><<<MTILES, 256, SMEM32>>>(Ghi, Glo, W4hi, W4lo, H1, NN);

    // --- final aggregation + log-softmax ---
    k_agg32_lsm<<<agg32_blocks, TB>>>(H1, out, csr, off, dinv, b4);
}